// round 16
// baseline (speedup 1.0000x reference)
#include <cuda_runtime.h>
#include <cuda_bf16.h>
#include <cuda_fp16.h>
#include <cstdint>

// ---------------------------------------------------------------------------
// Problem constants
// ---------------------------------------------------------------------------
#define N_NODES   2048
#define L_SEQ     100
#define D_IN      128
#define D_STATE   16
#define D_INNER   256
#define MAMBA_DIM 128
#define GAT_HID   64
#define HEADS     4
#define GAT_OUT   64
#define N_TOK     (N_NODES * L_SEQ)          // 204800
#define N_TILES   (N_TOK / 128)              // 1600
#define MAX_DEG   96

// ---------------------------------------------------------------------------
// Device scratch
// ---------------------------------------------------------------------------
__device__ float g_B[N_TOK * D_STATE];
__device__ float g_C[N_TOK * D_STATE];
__device__ float g_Wcomb[D_STATE * MAMBA_DIM];
__device__ float g_bcomb[MAMBA_DIM];
__device__ float g_xt1[HEADS * N_NODES * GAT_HID];
__device__ float g_es1[HEADS * N_NODES];
__device__ float g_ed1[HEADS * N_NODES];
__device__ float g_h1[N_NODES * HEADS * GAT_HID];
__device__ float g_xt2[N_NODES * GAT_OUT];
__device__ float g_es2[N_NODES];
__device__ float g_ed2[N_NODES];
__device__ unsigned short g_nbr[N_NODES * MAX_DEG];
__device__ int g_deg[N_NODES];

// pre-packed fp16 operands (swizzled smem images)
__device__ uint32_t g_Wh[4 * 128 * 64];
__device__ unsigned short g_Wbh16[16 * 256];
__device__ unsigned short g_Wbl16[16 * 256];
__device__ uint32_t g_Wch[16 * 64];
__device__ uint32_t g_Wcl[16 * 64];

// ---------------------------------------------------------------------------
// PTX helpers (plain sm_80-era; valid for compute_103 target)
// ---------------------------------------------------------------------------
__device__ __forceinline__ uint32_t smem_u32(const void* p) {
    uint32_t a;
    asm("{ .reg .u64 t; cvta.to.shared.u64 t, %1; cvt.u32.u64 %0, t; }" : "=r"(a) : "l"(p));
    return a;
}

__device__ __forceinline__ void ldsm4(uint32_t* r, uint32_t addr) {
    asm volatile("ldmatrix.sync.aligned.m8n8.x4.shared.b16 {%0,%1,%2,%3}, [%4];"
        : "=r"(r[0]), "=r"(r[1]), "=r"(r[2]), "=r"(r[3]) : "r"(addr));
}

__device__ __forceinline__ void mma_f16(float* d, const uint32_t* a, uint32_t b0, uint32_t b1) {
    asm volatile("mma.sync.aligned.m16n8k16.row.col.f32.f16.f16.f32 "
        "{%0,%1,%2,%3}, {%4,%5,%6,%7}, {%8,%9}, {%0,%1,%2,%3};"
        : "+f"(d[0]), "+f"(d[1]), "+f"(d[2]), "+f"(d[3])
        : "r"(a[0]), "r"(a[1]), "r"(a[2]), "r"(a[3]), "r"(b0), "r"(b1));
}

__device__ __forceinline__ void cp_async16(uint32_t saddr, const void* gptr) {
    asm volatile("cp.async.cg.shared.global [%0], [%1], 16;" :: "r"(saddr), "l"(gptr));
}
#define CP_COMMIT() asm volatile("cp.async.commit_group;" ::: "memory")
#define CP_WAIT0()  asm volatile("cp.async.wait_group 0;" ::: "memory")

__device__ __forceinline__ uint32_t pack_hl_f16(float v0, float v1, uint32_t& lo)
{
    __half h0 = __float2half_rn(v0), h1 = __float2half_rn(v1);
    __half l0 = __float2half_rn(v0 - __half2float(h0));
    __half l1 = __float2half_rn(v1 - __half2float(h1));
    lo = (uint32_t)__half_as_ushort(l0) | ((uint32_t)__half_as_ushort(l1) << 16);
    return (uint32_t)__half_as_ushort(h0) | ((uint32_t)__half_as_ushort(h1) << 16);
}
__device__ __forceinline__ uint32_t pack_f16(float v0, float v1)
{
    __half h0 = __float2half_rn(v0), h1 = __float2half_rn(v1);
    return (uint32_t)__half_as_ushort(h0) | ((uint32_t)__half_as_ushort(h1) << 16);
}

// ---------------------------------------------------------------------------
// PREP: prep_w + combine only (147 blocks; x pack moved into mamba prologue)
// ---------------------------------------------------------------------------
#define GRID_PREP 147

__global__ void mega_prep_kernel(
    const float* __restrict__ Wi, const float* __restrict__ Wg,
    const float* __restrict__ Wb, const float* __restrict__ Wc,
    const float* __restrict__ Wo, const float* __restrict__ bo,
    const float* __restrict__ Wfc, const float* __restrict__ bfc)
{
    const int b = blockIdx.x;
    const int tid = threadIdx.x;   // 256

    if (b < 128) {
        int w = b * 256 + tid;
        int c = w >> 13, r = w & 8191, n = r >> 6, kp = r & 63;
        const float* W = (n < 64) ? Wi : Wg;
        int col = c * 64 + (n & 63);
        float v0 = W[(size_t)(2 * kp) * 256 + col];
        float v1 = W[(size_t)(2 * kp + 1) * 256 + col];
        int word = (((kp >> 2) ^ (n & 7)) << 2) | (kp & 3);
        g_Wh[c * 8192 + n * 64 + word] = pack_f16(v0, v1);
    } else if (b == 128) {
        for (int u = tid; u < 4096; u += 256) {
            int s = u >> 8, j = u & 255;
            float v = Wb[(size_t)j * 16 + s];
            __half hh = __float2half_rn(v);
            __half ll = __float2half_rn(v - __half2float(hh));
            int hw = s * 256 + ((((j >> 3) ^ (s & 7)) << 3) | (j & 7));
            g_Wbh16[hw] = __half_as_ushort(hh);
            g_Wbl16[hw] = __half_as_ushort(ll);
        }
    } else if (b == 129) {
        for (int u = tid; u < 1024; u += 256) {
            int s = u >> 6, kp = u & 63;
            float v0 = Wc[(size_t)(2 * kp) * 16 + s];
            float v1 = Wc[(size_t)(2 * kp + 1) * 16 + s];
            uint32_t lo, hi = pack_hl_f16(v0, v1, lo);
            int word = s * 64 + ((((kp >> 2) ^ (s & 7)) << 2) | (kp & 3));
            g_Wch[word] = hi;
            g_Wcl[word] = lo;
        }
    } else {
        const int d = b - 130;   // 0..16
        if (tid < 128) {
            int j = tid;
            if (d < D_STATE) {
                float acc = 0.f;
                for (int mid = 0; mid < 128; ++mid)
                    acc += Wo[d * 128 + mid] * Wfc[mid * 128 + j];
                g_Wcomb[d * 128 + j] = acc;
            } else {
                float bb2 = bfc[j];
                for (int mid = 0; mid < 128; ++mid)
                    bb2 += bo[mid] * Wfc[mid * 128 + j];
                g_bcomb[j] = bb2;
            }
        }
    }
}

// ---------------------------------------------------------------------------
// Mamba kernel + trailing blocks (CSR build, gat1 transform)
//   [0, 1600)        mamba tiles (x packed in-prologue from temporal+pos)
//   [1600, 3648)     CSR build (512 threads)
//   [3648, 3776)     gat1 transform (16 nodes, 512 threads)
// ---------------------------------------------------------------------------
#define O_XH  0
#define O_W   32768
#define O_WBH 65536
#define O_WBL 73728
#define O_WCH 81920
#define O_WCL 86016
#define O_BI  90112
#define O_BG  91136
#define SMEM_MAMBA 92160
#define O_RED O_WCH
#define GT1_NODES 16
#define MB_CSR N_TILES
#define MB_GT  (MB_CSR + N_NODES)
#define GRID_MAMBA (MB_GT + N_NODES / GT1_NODES)

__global__ void __launch_bounds__(512, 2) mamba_mma_kernel(
    const float* __restrict__ temporal, const float* __restrict__ pos,
    const float* __restrict__ bi, const float* __restrict__ bg,
    const float* __restrict__ bb, const float* __restrict__ bc,
    const float* __restrict__ adj,
    const float* __restrict__ gx, const float* __restrict__ W1,
    const float* __restrict__ a1)
{
    extern __shared__ char sm[];
    const uint32_t smb = smem_u32(sm);
    const int blk = blockIdx.x;
    const int tid = threadIdx.x, wid = tid >> 5, lane = tid & 31;

    if (blk >= MB_GT) {
        // ================= gat1 transform (16 nodes, 512 threads) ==========
        const int n0 = (blk - MB_GT) * GT1_NODES;
        const int h = (tid >> 6) & 3, o = tid & 63, ng = tid >> 8;
        float* xr  = (float*)sm;
        float* red = (float*)sm + GT1_NODES * 128;

        for (int u = tid; u < GT1_NODES * 128; u += 512)
            xr[u] = gx[(size_t)n0 * 128 + u];
        __syncthreads();

        float acc[8];
        #pragma unroll
        for (int r = 0; r < 8; ++r) acc[r] = 0.f;
        const float* w = W1 + h * (128 * 64) + o;
        #pragma unroll 4
        for (int k = 0; k < 128; ++k) {
            float wv = w[k * 64];
            #pragma unroll
            for (int r = 0; r < 8; ++r) acc[r] += xr[(ng * 8 + r) * 128 + k] * wv;
        }
        #pragma unroll
        for (int r = 0; r < 8; ++r)
            g_xt1[((size_t)h * N_NODES + n0 + ng * 8 + r) * 64 + o] = acc[r];

        const float as = a1[h * 128 + o], ad = a1[h * 128 + 64 + o];
        const int wh = (o >> 5);
        #pragma unroll
        for (int r = 0; r < 8; ++r) {
            float ps = acc[r] * as;
            float pd = acc[r] * ad;
            #pragma unroll
            for (int off = 16; off; off >>= 1) {
                ps += __shfl_xor_sync(0xffffffffu, ps, off);
                pd += __shfl_xor_sync(0xffffffffu, pd, off);
            }
            if ((o & 31) == 0) {
                red[((0 * HEADS + h) * 2 + wh) * GT1_NODES + ng * 8 + r] = ps;
                red[((1 * HEADS + h) * 2 + wh) * GT1_NODES + ng * 8 + r] = pd;
            }
        }
        __syncthreads();
        if (tid < HEADS * GT1_NODES) {
            int h2 = tid / GT1_NODES, r2 = tid % GT1_NODES;
            g_es1[h2 * N_NODES + n0 + r2] =
                red[((0 * HEADS + h2) * 2 + 0) * GT1_NODES + r2] +
                red[((0 * HEADS + h2) * 2 + 1) * GT1_NODES + r2];
            g_ed1[h2 * N_NODES + n0 + r2] =
                red[((1 * HEADS + h2) * 2 + 0) * GT1_NODES + r2] +
                red[((1 * HEADS + h2) * 2 + 1) * GT1_NODES + r2];
        }
        return;
    }

    if (blk >= MB_CSR) {
        // ================= CSR build (512 threads) ==========================
        const int i = blk - MB_CSR;
        int* cntp = (int*)(sm + 8192);
        unsigned short* loc = (unsigned short*)sm;
        if (tid == 0) *cntp = 0;
        __syncthreads();
        const float4* row = (const float4*)(adj + (size_t)i * N_NODES);
        for (int u = tid; u < N_NODES / 4; u += 512) {
            float4 v = row[u];
            if (v.x > 0.f) { int p = atomicAdd(cntp, 1); if (p < MAX_DEG) loc[p] = (unsigned short)(4 * u); }
            if (v.y > 0.f) { int p = atomicAdd(cntp, 1); if (p < MAX_DEG) loc[p] = (unsigned short)(4 * u + 1); }
            if (v.z > 0.f) { int p = atomicAdd(cntp, 1); if (p < MAX_DEG) loc[p] = (unsigned short)(4 * u + 2); }
            if (v.w > 0.f) { int p = atomicAdd(cntp, 1); if (p < MAX_DEG) loc[p] = (unsigned short)(4 * u + 3); }
        }
        __syncthreads();
        int m = *cntp < MAX_DEG ? *cntp : MAX_DEG;
        if (tid == 0) g_deg[i] = m;
        if (tid < m) g_nbr[i * MAX_DEG + tid] = loc[tid];
        return;
    }

    // ================= mamba tile =======================
    const int grp = wid & 7;
    const int h   = wid >> 3;
    const int mbase = blk * 128;

    {
        // async weights first (in flight while we pack x)
        const uint4* wsrc = (const uint4*)g_Wh;
        for (int i = tid; i < 2048; i += 512)
            cp_async16(smb + O_W + i * 16, wsrc + i);
        if (tid < 512) {
            cp_async16(smb + O_WBH + tid * 16, (const uint4*)g_Wbh16 + tid);
            cp_async16(smb + O_WBL + tid * 16, (const uint4*)g_Wbl16 + tid);
        }
        if (tid < 256) {
            cp_async16(smb + O_WCH + tid * 16, (const uint4*)g_Wch + tid);
            cp_async16(smb + O_WCL + tid * 16, (const uint4*)g_Wcl + tid);
        }
        if (tid < 64)       cp_async16(smb + O_BI + tid * 16, (const uint4*)bi + tid);
        else if (tid < 128) cp_async16(smb + O_BG + (tid - 64) * 16, (const uint4*)bg + (tid - 64));
        CP_COMMIT();

        // pack x directly from temporal+pos into swizzled smem (overlaps cp.async)
        for (int u = tid; u < 8192; u += 512) {
            int t = u >> 6, kp = u & 63;
            int m = mbase + t;
            float2 tv = *(const float2*)(temporal + (size_t)m * 128 + 2 * kp);
            float2 pv = *(const float2*)(pos + (size_t)(m % L_SEQ) * 128 + 2 * kp);
            uint32_t off = (uint32_t)(t * 256 + (((((kp >> 2) ^ (t & 7)) << 2) | (kp & 3)) << 2));
            *(uint32_t*)(sm + O_XH + off) = pack_f16(tv.x + pv.x, tv.y + pv.y);
        }
        CP_WAIT0();
        __syncthreads();
    }

    const int trow = 16 * grp + (lane & 15);
    const uint32_t a_u = (uint32_t)(lane >> 4);
    const int nrb = (lane & 7) + ((lane >> 4) << 3);
    const uint32_t b_u = (uint32_t)((lane >> 3) & 1);
    const int rr = 16 * grp + (lane >> 2);
    const int cb = (lane & 3) * 2;

    // ---- C = x@Wc via MMA, cross-half reduce ----
    {
        float Cacc[2][4];
        #pragma unroll
        for (int q = 0; q < 2; ++q)
            #pragma unroll
            for (int r = 0; r < 4; ++r) Cacc[q][r] = 0.f;
        const uint32_t wcb = smb + (h ? O_WCL : O_WCH);
        #pragma unroll
        for (int kt = 0; kt < 8; ++kt) {
            uint32_t Ah[4];
            ldsm4(Ah, smb + O_XH + (uint32_t)(trow * 256 + ((((2 * kt + a_u) ^ (trow & 7)) & 15) << 4)));
            uint32_t bw[4];
            ldsm4(bw, wcb + (uint32_t)(nrb * 256 + ((((2 * kt + b_u) ^ (nrb & 7)) & 15) << 4)));
            mma_f16(Cacc[0], Ah, bw[0], bw[1]);
            mma_f16(Cacc[1], Ah, bw[2], bw[3]);
        }
        __syncthreads();
        float* red = (float*)(sm + O_RED);
        if (h == 1) {
            red[rr * 16 + cb]           = Cacc[0][0];
            red[rr * 16 + cb + 1]       = Cacc[0][1];
            red[rr * 16 + 8 + cb]       = Cacc[1][0];
            red[rr * 16 + 8 + cb + 1]   = Cacc[1][1];
            red[(rr + 8) * 16 + cb]     = Cacc[0][2];
            red[(rr + 8) * 16 + cb + 1] = Cacc[0][3];
            red[(rr + 8) * 16 + 8 + cb]     = Cacc[1][2];
            red[(rr + 8) * 16 + 8 + cb + 1] = Cacc[1][3];
        }
        __syncthreads();
        if (h == 0) {
            float2 bc0 = *(const float2*)(bc + cb);
            float2 bc1 = *(const float2*)(bc + 8 + cb);
            *(float2*)(&g_C[(size_t)(mbase + rr) * 16 + cb]) =
                make_float2(Cacc[0][0] + red[rr * 16 + cb] + bc0.x,
                            Cacc[0][1] + red[rr * 16 + cb + 1] + bc0.y);
            *(float2*)(&g_C[(size_t)(mbase + rr) * 16 + 8 + cb]) =
                make_float2(Cacc[1][0] + red[rr * 16 + 8 + cb] + bc1.x,
                            Cacc[1][1] + red[rr * 16 + 8 + cb + 1] + bc1.y);
            *(float2*)(&g_C[(size_t)(mbase + rr + 8) * 16 + cb]) =
                make_float2(Cacc[0][2] + red[(rr + 8) * 16 + cb] + bc0.x,
                            Cacc[0][3] + red[(rr + 8) * 16 + cb + 1] + bc0.y);
            *(float2*)(&g_C[(size_t)(mbase + rr + 8) * 16 + 8 + cb]) =
                make_float2(Cacc[1][2] + red[(rr + 8) * 16 + 8 + cb] + bc1.x,
                            Cacc[1][3] + red[(rr + 8) * 16 + 8 + cb + 1] + bc1.y);
        }
    }

    // ---- main loop ----
    float Bacc[2][4];
    #pragma unroll
    for (int q = 0; q < 2; ++q)
        #pragma unroll
        for (int r = 0; r < 4; ++r) Bacc[q][r] = 0.f;

    const float* bi_s = (const float*)(sm + O_BI);
    const float* bg_s = (const float*)(sm + O_BG);

    for (int c = 0; c < 4; ++c) {
        float acc[8][4];
        #pragma unroll
        for (int nt = 0; nt < 8; ++nt)
            #pragma unroll
            for (int r = 0; r < 4; ++r) acc[nt][r] = 0.f;

        #pragma unroll
        for (int kt = 0; kt < 8; ++kt) {
            uint32_t Ah[4];
            ldsm4(Ah, smb + O_XH + (uint32_t)(trow * 256 + ((((2 * kt + a_u) ^ (trow & 7)) & 15) << 4)));
            #pragma unroll
            for (int q = 0; q < 4; ++q) {
                int nb = ((q < 2) ? 0 : 64) + h * 32 + (q & 1) * 16 + nrb;
                uint32_t bw[4];
                ldsm4(bw, smb + O_W + (uint32_t)(nb * 256 + ((((2 * kt + b_u) ^ (nb & 7)) & 15) << 4)));
                mma_f16(acc[2 * q],     Ah, bw[0], bw[1]);
                mma_f16(acc[2 * q + 1], Ah, bw[2], bw[3]);
            }
        }
        __syncthreads();

        if (c < 3) {
            const uint4* wsrc = (const uint4*)g_Wh + (c + 1) * 2048;
            for (int i = tid; i < 2048; i += 512)
                cp_async16(smb + O_W + i * 16, wsrc + i);
            CP_COMMIT();
        }

        #pragma unroll
        for (int jt = 0; jt < 2; ++jt) {
            uint32_t Agh[4], Agl[4];
            #pragma unroll
            for (int half = 0; half < 2; ++half) {
                int ivt = 2 * jt + half, gxt = 4 + 2 * jt + half;
                int colb = c * 64 + h * 32 + jt * 16 + half * 8 + cb;
                float bix = bi_s[colb], biy = bi_s[colb + 1];
                float bgx = bg_s[colb], bgy = bg_s[colb + 1];
                float iv0 = acc[ivt][0] + bix, gx0 = acc[gxt][0] + bgx;
                float iv1 = acc[ivt][1] + biy, gx1 = acc[gxt][1] + bgy;
                float iv2 = acc[ivt][2] + bix, gx2 = acc[gxt][2] + bgx;
                float iv3 = acc[ivt][3] + biy, gx3 = acc[gxt][3] + bgy;
                float g0 = iv0 / (1.f + __expf(-gx0));
                float g1 = iv1 / (1.f + __expf(-gx1));
                float g2 = iv2 / (1.f + __expf(-gx2));
                float g3 = iv3 / (1.f + __expf(-gx3));
                Agh[half * 2 + 0] = pack_hl_f16(g0, g1, Agl[half * 2 + 0]);
                Agh[half * 2 + 1] = pack_hl_f16(g2, g3, Agl[half * 2 + 1]);
            }
            uint32_t idx = (uint32_t)(c * 8 + h * 4 + jt * 2) + b_u;
            uint32_t su = (uint32_t)(nrb * 512) + (((idx ^ (uint32_t)(nrb & 7)) & 31u) << 4);
            uint32_t wbh[4], wbl[4];
            ldsm4(wbh, smb + O_WBH + su);
            ldsm4(wbl, smb + O_WBL + su);
            mma_f16(Bacc[0], Agh, wbh[0], wbh[1]);
            mma_f16(Bacc[1], Agh, wbh[2], wbh[3]);
            mma_f16(Bacc[0], Agh, wbl[0], wbl[1]);
            mma_f16(Bacc[1], Agh, wbl[2], wbl[3]);
            mma_f16(Bacc[0], Agl, wbh[0], wbh[1]);
            mma_f16(Bacc[1], Agl, wbh[2], wbh[3]);
        }
        if (c < 3) { CP_WAIT0(); __syncthreads(); }
    }

    // ---- cross-warp B reduction (+bb) ----
    __syncthreads();
    {
        float* red = (float*)(sm + O_RED);
        if (h == 1) {
            red[rr * 16 + cb]           = Bacc[0][0];
            red[rr * 16 + cb + 1]       = Bacc[0][1];
            red[rr * 16 + 8 + cb]       = Bacc[1][0];
            red[rr * 16 + 8 + cb + 1]   = Bacc[1][1];
            red[(rr + 8) * 16 + cb]     = Bacc[0][2];
            red[(rr + 8) * 16 + cb + 1] = Bacc[0][3];
            red[(rr + 8) * 16 + 8 + cb]     = Bacc[1][2];
            red[(rr + 8) * 16 + 8 + cb + 1] = Bacc[1][3];
        }
        __syncthreads();
        if (h == 0) {
            float2 bb0 = *(const float2*)(bb + cb);
            float2 bb1 = *(const float2*)(bb + 8 + cb);
            *(float2*)(&g_B[(size_t)(mbase + rr) * 16 + cb]) =
                make_float2(Bacc[0][0] + red[rr * 16 + cb] + bb0.x,
                            Bacc[0][1] + red[rr * 16 + cb + 1] + bb0.y);
            *(float2*)(&g_B[(size_t)(mbase + rr) * 16 + 8 + cb]) =
                make_float2(Bacc[1][0] + red[rr * 16 + 8 + cb] + bb1.x,
                            Bacc[1][1] + red[rr * 16 + 8 + cb + 1] + bb1.y);
            *(float2*)(&g_B[(size_t)(mbase + rr + 8) * 16 + cb]) =
                make_float2(Bacc[0][2] + red[(rr + 8) * 16 + cb] + bb0.x,
                            Bacc[0][3] + red[(rr + 8) * 16 + cb + 1] + bb0.y);
            *(float2*)(&g_B[(size_t)(mbase + rr + 8) * 16 + 8 + cb]) =
                make_float2(Bacc[1][2] + red[(rr + 8) * 16 + 8 + cb] + bb1.x,
                            Bacc[1][3] + red[(rr + 8) * 16 + 8 + cb + 1] + bb1.y);
        }
    }
}

// ---------------------------------------------------------------------------
// MEGA-MID: scan_out [0,2048) + gat1_attn [2048,4096)
// ---------------------------------------------------------------------------
__global__ void mega_mid_kernel(const float* __restrict__ A_log, float* __restrict__ out)
{
    const int blk = blockIdx.x;
    const int tid = threadIdx.x;   // 256
    __shared__ float Bs[L_SEQ * D_STATE];
    __shared__ float Cs[L_SEQ * D_STATE];
    __shared__ unsigned short nbr[MAX_DEG];
    __shared__ float att[HEADS][MAX_DEG];

    if (blk < N_NODES) {
        const int n = blk;
        for (int idx = tid; idx < L_SEQ * D_STATE; idx += 256) {
            Bs[idx] = g_B[(size_t)n * L_SEQ * D_STATE + idx];
            Cs[idx] = g_C[(size_t)n * L_SEQ * D_STATE + idx];
        }
        __syncthreads();
        if (tid < D_STATE) {
            float Av = expf(0.01f * expf(A_log[tid]));
            float h = 0.f;
            for (int t = 0; t < L_SEQ; ++t) {
                h = Av * h + Bs[t * D_STATE + tid];
                Bs[t * D_STATE + tid] = h * Cs[t * D_STATE + tid];
            }
        }
        __syncthreads();
        if (tid < 128) {
            float wc[D_STATE];
            #pragma unroll
            for (int d = 0; d < D_STATE; ++d) wc[d] = g_Wcomb[d * 128 + tid];
            float bj = g_bcomb[tid];
            float* op = out + (size_t)n * L_SEQ * MAMBA_DIM + tid;
            for (int t = 0; t < L_SEQ; ++t) {
                float acc = bj;
                #pragma unroll
                for (int d = 0; d < D_STATE; ++d) acc += Bs[t * D_STATE + d] * wc[d];
                op[(size_t)t * MAMBA_DIM] = acc;
            }
        }
    } else {
        const int i = blk - N_NODES;
        const int m = g_deg[i];
        if (tid < m) nbr[tid] = g_nbr[i * MAX_DEG + tid];
        __syncthreads();

        if (tid < 128) {
            const int h = tid >> 5, lane = tid & 31;
            const float esrc = g_es1[h * N_NODES + i];
            float emax = -1e30f;
            for (int s = lane; s < m; s += 32) {
                float e = esrc + g_ed1[h * N_NODES + (int)nbr[s]];
                e = e > 0.f ? e : 0.2f * e;
                att[h][s] = e;
                emax = fmaxf(emax, e);
            }
            #pragma unroll
            for (int off = 16; off; off >>= 1)
                emax = fmaxf(emax, __shfl_xor_sync(0xffffffffu, emax, off));
            float esum = 0.f;
            for (int s = lane; s < m; s += 32) {
                float v = __expf(att[h][s] - emax);
                att[h][s] = v; esum += v;
            }
            #pragma unroll
            for (int off = 16; off; off >>= 1)
                esum += __shfl_xor_sync(0xffffffffu, esum, off);
            float inv = 1.f / esum;
            for (int s = lane; s < m; s += 32) att[h][s] *= inv;
        }
        __syncthreads();

        const int h = tid >> 6, o = tid & 63;
        float acc = 0.f;
        for (int s = 0; s < m; ++s)
            acc += att[h][s] * g_xt1[((size_t)h * N_NODES + (int)nbr[s]) * 64 + o];
        g_h1[(size_t)i * 256 + h * 64 + o] = fmaxf(acc, 0.f);
    }
}

// ---------------------------------------------------------------------------
// GAT layer 2: transform, 4 nodes/block
// ---------------------------------------------------------------------------
#define GT2_NODES 4
__global__ void gat2_transform_kernel(const float* __restrict__ W2,
                                      const float* __restrict__ a2)
{
    const int n0 = blockIdx.x * GT2_NODES;   // grid 512
    const int tid = threadIdx.x;             // 256
    const int kg = tid >> 6, o = tid & 63;
    __shared__ float hr[GT2_NODES][256];
    __shared__ float part[4][GT2_NODES][64];
    __shared__ float red[2][2][GT2_NODES];

    for (int u = tid; u < GT2_NODES * 256; u += 256)
        hr[u >> 8][u & 255] = g_h1[(size_t)(n0 + (u >> 8)) * 256 + (u & 255)];
    __syncthreads();

    float acc[GT2_NODES];
    #pragma unroll
    for (int r = 0; r < GT2_NODES; ++r) acc[r] = 0.f;
    #pragma unroll 4
    for (int kk = 0; kk < 64; ++kk) {
        int k = kg * 64 + kk;
        float wv = W2[k * 64 + o];
        #pragma unroll
        for (int r = 0; r < GT2_NODES; ++r) acc[r] += hr[r][k] * wv;
    }
    #pragma unroll
    for (int r = 0; r < GT2_NODES; ++r) part[kg][r][o] = acc[r];
    __syncthreads();

    if (kg == 0) {
        const float as = a2[o], ad = a2[64 + o];
        const int wh = o >> 5;
        #pragma unroll
        for (int r = 0; r < GT2_NODES; ++r) {
            float v = part[0][r][o] + part[1][r][o] + part[2][r][o] + part[3][r][o];
            g_xt2[(size_t)(n0 + r) * 64 + o] = v;
            float ps = v * as, pd = v * ad;
            #pragma unroll
            for (int off = 16; off; off >>= 1) {
                ps += __shfl_xor_sync(0xffffffffu, ps, off);
                pd += __shfl_xor_sync(0xffffffffu, pd, off);
            }
            if ((o & 31) == 0) { red[0][wh][r] = ps; red[1][wh][r] = pd; }
        }
    }
    __syncthreads();
    if (tid < GT2_NODES) {
        g_es2[n0 + tid] = red[0][0][tid] + red[0][1][tid];
        g_ed2[n0 + tid] = red[1][0][tid] + red[1][1][tid];
    }
}

// ---------------------------------------------------------------------------
// GAT layer 2: sparse attention + aggregation
// ---------------------------------------------------------------------------
__global__ void gat2_attn_kernel(float* __restrict__ outg)
{
    const int i = blockIdx.x;
    __shared__ unsigned short nbr[MAX_DEG];
    __shared__ float att[MAX_DEG];
    const int tid = threadIdx.x;   // 128
    const int m = g_deg[i];
    if (tid < m) nbr[tid] = g_nbr[i * MAX_DEG + tid];
    __syncthreads();

    if (tid < 32) {
        const float esrc = g_es2[i];
        float emax = -1e30f;
        for (int s = tid; s < m; s += 32) {
            float e = esrc + g_ed2[(int)nbr[s]];
            e = e > 0.f ? e : 0.2f * e;
            att[s] = e;
            emax = fmaxf(emax, e);
        }
        #pragma unroll
        for (int off = 16; off; off >>= 1)
            emax = fmaxf(emax, __shfl_xor_sync(0xffffffffu, emax, off));
        float esum = 0.f;
        for (int s = tid; s < m; s += 32) {
            float v = __expf(att[s] - emax);
            att[s] = v; esum += v;
        }
        #pragma unroll
        for (int off = 16; off; off >>= 1)
            esum += __shfl_xor_sync(0xffffffffu, esum, off);
        float inv = 1.f / esum;
        for (int s = tid; s < m; s += 32) att[s] *= inv;
    }
    __syncthreads();

    if (tid < 64) {
        float acc = 0.f;
        for (int s = 0; s < m; ++s)
            acc += att[s] * g_xt2[(size_t)((int)nbr[s]) * 64 + tid];
        outg[(size_t)i * 64 + tid] = acc;
    }
}

// ---------------------------------------------------------------------------
// Launch: 5 kernels
// ---------------------------------------------------------------------------
extern "C" void kernel_launch(void* const* d_in, const int* in_sizes, int n_in,
                              void* d_out, int out_size)
{
    const float* temporal = (const float*)d_in[0];
    const float* graph_x  = (const float*)d_in[1];
    const float* adj      = (const float*)d_in[2];
    const float* pos      = (const float*)d_in[3];
    const float* Wi       = (const float*)d_in[4];
    const float* bi       = (const float*)d_in[5];
    const float* Wg       = (const float*)d_in[6];
    const float* bg       = (const float*)d_in[7];
    const float* A_log    = (const float*)d_in[8];
    const float* Wb       = (const float*)d_in[9];
    const float* bb       = (const float*)d_in[10];
    const float* Wc       = (const float*)d_in[11];
    const float* bc       = (const float*)d_in[12];
    const float* Wo       = (const float*)d_in[13];
    const float* bo       = (const float*)d_in[14];
    const float* Wfc      = (const float*)d_in[15];
    const float* bfc      = (const float*)d_in[16];
    const float* W1       = (const float*)d_in[17];
    const float* a1       = (const float*)d_in[18];
    const float* W2       = (const float*)d_in[19];
    const float* a2       = (const float*)d_in[20];

    float* out_mamba = (float*)d_out;
    float* out_gat   = out_mamba + (size_t)N_NODES * L_SEQ * MAMBA_DIM;

    cudaFuncSetAttribute(mamba_mma_kernel,
                         cudaFuncAttributeMaxDynamicSharedMemorySize, SMEM_MAMBA);

    mega_prep_kernel<<<GRID_PREP, 256>>>(
        Wi, Wg, Wb, Wc, Wo, bo, Wfc, bfc);                          // idx 0
    mamba_mma_kernel<<<GRID_MAMBA, 512, SMEM_MAMBA>>>(
        temporal, pos, bi, bg, bb, bc, adj, graph_x, W1, a1);       // idx 1
    mega_mid_kernel<<<2 * N_NODES, 256>>>(A_log, out_mamba);        // idx 2
    gat2_transform_kernel<<<N_NODES / GT2_NODES, 256>>>(W2, a2);    // idx 3
    gat2_attn_kernel<<<N_NODES, 128>>>(out_gat);                    // idx 4
}

// round 17
// speedup vs baseline: 1.0520x; 1.0520x over previous
#include <cuda_runtime.h>
#include <cuda_bf16.h>
#include <cuda_fp16.h>
#include <cstdint>

// ---------------------------------------------------------------------------
// Problem constants
// ---------------------------------------------------------------------------
#define N_NODES   2048
#define L_SEQ     100
#define D_IN      128
#define D_STATE   16
#define D_INNER   256
#define MAMBA_DIM 128
#define GAT_HID   64
#define HEADS     4
#define GAT_OUT   64
#define N_TOK     (N_NODES * L_SEQ)          // 204800
#define N_TILES   (N_TOK / 128)              // 1600
#define MAX_DEG   96

// ---------------------------------------------------------------------------
// Device scratch
// ---------------------------------------------------------------------------
__device__ float g_B[N_TOK * D_STATE];
__device__ float g_C[N_TOK * D_STATE];
__device__ float g_Wcomb[D_STATE * MAMBA_DIM];
__device__ float g_bcomb[MAMBA_DIM];
__device__ float g_xt1[HEADS * N_NODES * GAT_HID];
__device__ float g_es1[HEADS * N_NODES];
__device__ float g_ed1[HEADS * N_NODES];
__device__ float g_h1[N_NODES * HEADS * GAT_HID];
__device__ float g_xt2[N_NODES * GAT_OUT];
__device__ float g_es2[N_NODES];
__device__ float g_ed2[N_NODES];
__device__ unsigned short g_nbr[N_NODES * MAX_DEG];
__device__ int g_deg[N_NODES];

// pre-packed fp16 operands (swizzled smem images)
__device__ uint32_t g_Wh[4 * 128 * 64];
__device__ unsigned short g_Wbh16[16 * 256];
__device__ unsigned short g_Wbl16[16 * 256];
__device__ uint32_t g_Wch[16 * 64];
__device__ uint32_t g_Wcl[16 * 64];
__device__ uint32_t g_XH[(size_t)N_TILES * 8192];

// ---------------------------------------------------------------------------
// PTX helpers (plain sm_80-era; valid for compute_103 target)
// ---------------------------------------------------------------------------
__device__ __forceinline__ uint32_t smem_u32(const void* p) {
    uint32_t a;
    asm("{ .reg .u64 t; cvta.to.shared.u64 t, %1; cvt.u32.u64 %0, t; }" : "=r"(a) : "l"(p));
    return a;
}

__device__ __forceinline__ void ldsm4(uint32_t* r, uint32_t addr) {
    asm volatile("ldmatrix.sync.aligned.m8n8.x4.shared.b16 {%0,%1,%2,%3}, [%4];"
        : "=r"(r[0]), "=r"(r[1]), "=r"(r[2]), "=r"(r[3]) : "r"(addr));
}

__device__ __forceinline__ void mma_f16(float* d, const uint32_t* a, uint32_t b0, uint32_t b1) {
    asm volatile("mma.sync.aligned.m16n8k16.row.col.f32.f16.f16.f32 "
        "{%0,%1,%2,%3}, {%4,%5,%6,%7}, {%8,%9}, {%0,%1,%2,%3};"
        : "+f"(d[0]), "+f"(d[1]), "+f"(d[2]), "+f"(d[3])
        : "r"(a[0]), "r"(a[1]), "r"(a[2]), "r"(a[3]), "r"(b0), "r"(b1));
}

__device__ __forceinline__ void cp_async16(uint32_t saddr, const void* gptr) {
    asm volatile("cp.async.cg.shared.global [%0], [%1], 16;" :: "r"(saddr), "l"(gptr));
}
#define CP_COMMIT() asm volatile("cp.async.commit_group;" ::: "memory")
#define CP_WAIT0()  asm volatile("cp.async.wait_group 0;" ::: "memory")

__device__ __forceinline__ uint32_t pack_hl_f16(float v0, float v1, uint32_t& lo)
{
    __half h0 = __float2half_rn(v0), h1 = __float2half_rn(v1);
    __half l0 = __float2half_rn(v0 - __half2float(h0));
    __half l1 = __float2half_rn(v1 - __half2float(h1));
    lo = (uint32_t)__half_as_ushort(l0) | ((uint32_t)__half_as_ushort(l1) << 16);
    return (uint32_t)__half_as_ushort(h0) | ((uint32_t)__half_as_ushort(h1) << 16);
}
__device__ __forceinline__ uint32_t pack_f16(float v0, float v1)
{
    __half h0 = __float2half_rn(v0), h1 = __float2half_rn(v1);
    return (uint32_t)__half_as_ushort(h0) | ((uint32_t)__half_as_ushort(h1) << 16);
}

// ---------------------------------------------------------------------------
// MEGA-PREP: prep_x [0,1600) + prep_w/combine [1600,1747)
// ---------------------------------------------------------------------------
#define NB_PX   N_TILES
#define NB_PW   147
#define GRID_PREP (NB_PX + NB_PW)

__global__ void mega_prep_kernel(
    const float* __restrict__ temporal, const float* __restrict__ pos,
    const float* __restrict__ Wi, const float* __restrict__ Wg,
    const float* __restrict__ Wb, const float* __restrict__ Wc,
    const float* __restrict__ Wo, const float* __restrict__ bo,
    const float* __restrict__ Wfc, const float* __restrict__ bfc)
{
    const int blk = blockIdx.x;
    const int tid = threadIdx.x;   // 256

    if (blk < NB_PX) {
        // ---------------- prep_x ----------------
        const int tile = blk;
        for (int u = tid; u < 8192; u += 256) {
            int t = u >> 6, kp = u & 63;
            int m = tile * 128 + t;
            float2 tv = *(const float2*)(temporal + (size_t)m * 128 + 2 * kp);
            float2 pv = *(const float2*)(pos + (size_t)(m % L_SEQ) * 128 + 2 * kp);
            int word = (((kp >> 2) ^ (t & 7)) << 2) | (kp & 3);
            g_XH[(size_t)tile * 8192 + t * 64 + word] = pack_f16(tv.x + pv.x, tv.y + pv.y);
        }
    } else {
        // ---------------- prep_w + combine ----------------
        const int b = blk - NB_PX;   // 0..146
        if (b < 128) {
            int w = b * 256 + tid;
            int c = w >> 13, r = w & 8191, n = r >> 6, kp = r & 63;
            const float* W = (n < 64) ? Wi : Wg;
            int col = c * 64 + (n & 63);
            float v0 = W[(size_t)(2 * kp) * 256 + col];
            float v1 = W[(size_t)(2 * kp + 1) * 256 + col];
            int word = (((kp >> 2) ^ (n & 7)) << 2) | (kp & 3);
            g_Wh[c * 8192 + n * 64 + word] = pack_f16(v0, v1);
        } else if (b == 128) {
            for (int u = tid; u < 4096; u += 256) {
                int s = u >> 8, j = u & 255;
                float v = Wb[(size_t)j * 16 + s];
                __half hh = __float2half_rn(v);
                __half ll = __float2half_rn(v - __half2float(hh));
                int hw = s * 256 + ((((j >> 3) ^ (s & 7)) << 3) | (j & 7));
                g_Wbh16[hw] = __half_as_ushort(hh);
                g_Wbl16[hw] = __half_as_ushort(ll);
            }
        } else if (b == 129) {
            for (int u = tid; u < 1024; u += 256) {
                int s = u >> 6, kp = u & 63;
                float v0 = Wc[(size_t)(2 * kp) * 16 + s];
                float v1 = Wc[(size_t)(2 * kp + 1) * 16 + s];
                uint32_t lo, hi = pack_hl_f16(v0, v1, lo);
                int word = s * 64 + ((((kp >> 2) ^ (s & 7)) << 2) | (kp & 3));
                g_Wch[word] = hi;
                g_Wcl[word] = lo;
            }
        } else {
            const int d = b - 130;   // 0..16
            if (tid < 128) {
                int j = tid;
                if (d < D_STATE) {
                    float acc = 0.f;
                    for (int mid = 0; mid < 128; ++mid)
                        acc += Wo[d * 128 + mid] * Wfc[mid * 128 + j];
                    g_Wcomb[d * 128 + j] = acc;
                } else {
                    float bb2 = bfc[j];
                    for (int mid = 0; mid < 128; ++mid)
                        bb2 += bo[mid] * Wfc[mid * 128 + j];
                    g_bcomb[j] = bb2;
                }
            }
        }
    }
}

// ---------------------------------------------------------------------------
// Mamba kernel + trailing blocks (CSR build, gat1 transform)
//   [0, 1600)        mamba tiles (R8 plateau path)
//   [1600, 3648)     CSR build (512 threads)
//   [3648, 3776)     gat1 transform (16 nodes, 512 threads)
// ---------------------------------------------------------------------------
#define O_XH  0
#define O_W   32768
#define O_WBH 65536
#define O_WBL 73728
#define O_WCH 81920
#define O_WCL 86016
#define O_BI  90112
#define O_BG  91136
#define SMEM_MAMBA 92160
#define O_RED O_WCH
#define GT1_NODES 16
#define MB_CSR N_TILES
#define MB_GT  (MB_CSR + N_NODES)
#define GRID_MAMBA (MB_GT + N_NODES / GT1_NODES)

__global__ void __launch_bounds__(512, 2) mamba_mma_kernel(
    const float* __restrict__ bi, const float* __restrict__ bg,
    const float* __restrict__ bb, const float* __restrict__ bc,
    const float* __restrict__ adj,
    const float* __restrict__ gx, const float* __restrict__ W1,
    const float* __restrict__ a1)
{
    extern __shared__ char sm[];
    const uint32_t smb = smem_u32(sm);
    const int blk = blockIdx.x;
    const int tid = threadIdx.x, wid = tid >> 5, lane = tid & 31;

    if (blk >= MB_GT) {
        // ================= gat1 transform (16 nodes, 512 threads) ==========
        const int n0 = (blk - MB_GT) * GT1_NODES;
        const int h = (tid >> 6) & 3, o = tid & 63, ng = tid >> 8;
        float* xr  = (float*)sm;
        float* red = (float*)sm + GT1_NODES * 128;

        for (int u = tid; u < GT1_NODES * 128; u += 512)
            xr[u] = gx[(size_t)n0 * 128 + u];
        __syncthreads();

        float acc[8];
        #pragma unroll
        for (int r = 0; r < 8; ++r) acc[r] = 0.f;
        const float* w = W1 + h * (128 * 64) + o;
        #pragma unroll 4
        for (int k = 0; k < 128; ++k) {
            float wv = w[k * 64];
            #pragma unroll
            for (int r = 0; r < 8; ++r) acc[r] += xr[(ng * 8 + r) * 128 + k] * wv;
        }
        #pragma unroll
        for (int r = 0; r < 8; ++r)
            g_xt1[((size_t)h * N_NODES + n0 + ng * 8 + r) * 64 + o] = acc[r];

        const float as = a1[h * 128 + o], ad = a1[h * 128 + 64 + o];
        const int wh = (o >> 5);
        #pragma unroll
        for (int r = 0; r < 8; ++r) {
            float ps = acc[r] * as;
            float pd = acc[r] * ad;
            #pragma unroll
            for (int off = 16; off; off >>= 1) {
                ps += __shfl_xor_sync(0xffffffffu, ps, off);
                pd += __shfl_xor_sync(0xffffffffu, pd, off);
            }
            if ((o & 31) == 0) {
                red[((0 * HEADS + h) * 2 + wh) * GT1_NODES + ng * 8 + r] = ps;
                red[((1 * HEADS + h) * 2 + wh) * GT1_NODES + ng * 8 + r] = pd;
            }
        }
        __syncthreads();
        if (tid < HEADS * GT1_NODES) {
            int h2 = tid / GT1_NODES, r2 = tid % GT1_NODES;
            g_es1[h2 * N_NODES + n0 + r2] =
                red[((0 * HEADS + h2) * 2 + 0) * GT1_NODES + r2] +
                red[((0 * HEADS + h2) * 2 + 1) * GT1_NODES + r2];
            g_ed1[h2 * N_NODES + n0 + r2] =
                red[((1 * HEADS + h2) * 2 + 0) * GT1_NODES + r2] +
                red[((1 * HEADS + h2) * 2 + 1) * GT1_NODES + r2];
        }
        return;
    }

    if (blk >= MB_CSR) {
        // ================= CSR build (512 threads) ==========================
        const int i = blk - MB_CSR;
        int* cntp = (int*)(sm + 8192);
        unsigned short* loc = (unsigned short*)sm;
        if (tid == 0) *cntp = 0;
        __syncthreads();
        const float4* row = (const float4*)(adj + (size_t)i * N_NODES);
        for (int u = tid; u < N_NODES / 4; u += 512) {
            float4 v = row[u];
            if (v.x > 0.f) { int p = atomicAdd(cntp, 1); if (p < MAX_DEG) loc[p] = (unsigned short)(4 * u); }
            if (v.y > 0.f) { int p = atomicAdd(cntp, 1); if (p < MAX_DEG) loc[p] = (unsigned short)(4 * u + 1); }
            if (v.z > 0.f) { int p = atomicAdd(cntp, 1); if (p < MAX_DEG) loc[p] = (unsigned short)(4 * u + 2); }
            if (v.w > 0.f) { int p = atomicAdd(cntp, 1); if (p < MAX_DEG) loc[p] = (unsigned short)(4 * u + 3); }
        }
        __syncthreads();
        int m = *cntp < MAX_DEG ? *cntp : MAX_DEG;
        if (tid == 0) g_deg[i] = m;
        if (tid < m) g_nbr[i * MAX_DEG + tid] = loc[tid];
        return;
    }

    // ================= mamba tile (R8 path) =======================
    const int grp = wid & 7;
    const int h   = wid >> 3;
    const int mbase = blk * 128;

    {
        const uint4* xsrc = (const uint4*)g_XH + (size_t)blk * 2048;
        for (int i = tid; i < 2048; i += 512)
            cp_async16(smb + O_XH + i * 16, xsrc + i);
        const uint4* wsrc = (const uint4*)g_Wh;
        for (int i = tid; i < 2048; i += 512)
            cp_async16(smb + O_W + i * 16, wsrc + i);
        if (tid < 512) {
            cp_async16(smb + O_WBH + tid * 16, (const uint4*)g_Wbh16 + tid);
            cp_async16(smb + O_WBL + tid * 16, (const uint4*)g_Wbl16 + tid);
        }
        if (tid < 256) {
            cp_async16(smb + O_WCH + tid * 16, (const uint4*)g_Wch + tid);
            cp_async16(smb + O_WCL + tid * 16, (const uint4*)g_Wcl + tid);
        }
        if (tid < 64)       cp_async16(smb + O_BI + tid * 16, (const uint4*)bi + tid);
        else if (tid < 128) cp_async16(smb + O_BG + (tid - 64) * 16, (const uint4*)bg + (tid - 64));
        CP_COMMIT();
        CP_WAIT0();
        __syncthreads();
    }

    const int trow = 16 * grp + (lane & 15);
    const uint32_t a_u = (uint32_t)(lane >> 4);
    const int nrb = (lane & 7) + ((lane >> 4) << 3);
    const uint32_t b_u = (uint32_t)((lane >> 3) & 1);
    const int rr = 16 * grp + (lane >> 2);
    const int cb = (lane & 3) * 2;

    // ---- C = x@Wc via MMA, cross-half reduce ----
    {
        float Cacc[2][4];
        #pragma unroll
        for (int q = 0; q < 2; ++q)
            #pragma unroll
            for (int r = 0; r < 4; ++r) Cacc[q][r] = 0.f;
        const uint32_t wcb = smb + (h ? O_WCL : O_WCH);
        #pragma unroll
        for (int kt = 0; kt < 8; ++kt) {
            uint32_t Ah[4];
            ldsm4(Ah, smb + O_XH + (uint32_t)(trow * 256 + ((((2 * kt + a_u) ^ (trow & 7)) & 15) << 4)));
            uint32_t bw[4];
            ldsm4(bw, wcb + (uint32_t)(nrb * 256 + ((((2 * kt + b_u) ^ (nrb & 7)) & 15) << 4)));
            mma_f16(Cacc[0], Ah, bw[0], bw[1]);
            mma_f16(Cacc[1], Ah, bw[2], bw[3]);
        }
        __syncthreads();
        float* red = (float*)(sm + O_RED);
        if (h == 1) {
            red[rr * 16 + cb]           = Cacc[0][0];
            red[rr * 16 + cb + 1]       = Cacc[0][1];
            red[rr * 16 + 8 + cb]       = Cacc[1][0];
            red[rr * 16 + 8 + cb + 1]   = Cacc[1][1];
            red[(rr + 8) * 16 + cb]     = Cacc[0][2];
            red[(rr + 8) * 16 + cb + 1] = Cacc[0][3];
            red[(rr + 8) * 16 + 8 + cb]     = Cacc[1][2];
            red[(rr + 8) * 16 + 8 + cb + 1] = Cacc[1][3];
        }
        __syncthreads();
        if (h == 0) {
            float2 bc0 = *(const float2*)(bc + cb);
            float2 bc1 = *(const float2*)(bc + 8 + cb);
            *(float2*)(&g_C[(size_t)(mbase + rr) * 16 + cb]) =
                make_float2(Cacc[0][0] + red[rr * 16 + cb] + bc0.x,
                            Cacc[0][1] + red[rr * 16 + cb + 1] + bc0.y);
            *(float2*)(&g_C[(size_t)(mbase + rr) * 16 + 8 + cb]) =
                make_float2(Cacc[1][0] + red[rr * 16 + 8 + cb] + bc1.x,
                            Cacc[1][1] + red[rr * 16 + 8 + cb + 1] + bc1.y);
            *(float2*)(&g_C[(size_t)(mbase + rr + 8) * 16 + cb]) =
                make_float2(Cacc[0][2] + red[(rr + 8) * 16 + cb] + bc0.x,
                            Cacc[0][3] + red[(rr + 8) * 16 + cb + 1] + bc0.y);
            *(float2*)(&g_C[(size_t)(mbase + rr + 8) * 16 + 8 + cb]) =
                make_float2(Cacc[1][2] + red[(rr + 8) * 16 + 8 + cb] + bc1.x,
                            Cacc[1][3] + red[(rr + 8) * 16 + 8 + cb + 1] + bc1.y);
        }
    }

    // ---- main loop ----
    float Bacc[2][4];
    #pragma unroll
    for (int q = 0; q < 2; ++q)
        #pragma unroll
        for (int r = 0; r < 4; ++r) Bacc[q][r] = 0.f;

    const float* bi_s = (const float*)(sm + O_BI);
    const float* bg_s = (const float*)(sm + O_BG);

    for (int c = 0; c < 4; ++c) {
        float acc[8][4];
        #pragma unroll
        for (int nt = 0; nt < 8; ++nt)
            #pragma unroll
            for (int r = 0; r < 4; ++r) acc[nt][r] = 0.f;

        #pragma unroll
        for (int kt = 0; kt < 8; ++kt) {
            uint32_t Ah[4];
            ldsm4(Ah, smb + O_XH + (uint32_t)(trow * 256 + ((((2 * kt + a_u) ^ (trow & 7)) & 15) << 4)));
            #pragma unroll
            for (int q = 0; q < 4; ++q) {
                int nb = ((q < 2) ? 0 : 64) + h * 32 + (q & 1) * 16 + nrb;
                uint32_t bw[4];
                ldsm4(bw, smb + O_W + (uint32_t)(nb * 256 + ((((2 * kt + b_u) ^ (nb & 7)) & 15) << 4)));
                mma_f16(acc[2 * q],     Ah, bw[0], bw[1]);
                mma_f16(acc[2 * q + 1], Ah, bw[2], bw[3]);
            }
        }
        __syncthreads();

        if (c < 3) {
            const uint4* wsrc = (const uint4*)g_Wh + (c + 1) * 2048;
            for (int i = tid; i < 2048; i += 512)
                cp_async16(smb + O_W + i * 16, wsrc + i);
            CP_COMMIT();
        }

        #pragma unroll
        for (int jt = 0; jt < 2; ++jt) {
            uint32_t Agh[4], Agl[4];
            #pragma unroll
            for (int half = 0; half < 2; ++half) {
                int ivt = 2 * jt + half, gxt = 4 + 2 * jt + half;
                int colb = c * 64 + h * 32 + jt * 16 + half * 8 + cb;
                float bix = bi_s[colb], biy = bi_s[colb + 1];
                float bgx = bg_s[colb], bgy = bg_s[colb + 1];
                float iv0 = acc[ivt][0] + bix, gx0 = acc[gxt][0] + bgx;
                float iv1 = acc[ivt][1] + biy, gx1 = acc[gxt][1] + bgy;
                float iv2 = acc[ivt][2] + bix, gx2 = acc[gxt][2] + bgx;
                float iv3 = acc[ivt][3] + biy, gx3 = acc[gxt][3] + bgy;
                float g0 = iv0 / (1.f + __expf(-gx0));
                float g1 = iv1 / (1.f + __expf(-gx1));
                float g2 = iv2 / (1.f + __expf(-gx2));
                float g3 = iv3 / (1.f + __expf(-gx3));
                Agh[half * 2 + 0] = pack_hl_f16(g0, g1, Agl[half * 2 + 0]);
                Agh[half * 2 + 1] = pack_hl_f16(g2, g3, Agl[half * 2 + 1]);
            }
            uint32_t idx = (uint32_t)(c * 8 + h * 4 + jt * 2) + b_u;
            uint32_t su = (uint32_t)(nrb * 512) + (((idx ^ (uint32_t)(nrb & 7)) & 31u) << 4);
            uint32_t wbh[4], wbl[4];
            ldsm4(wbh, smb + O_WBH + su);
            ldsm4(wbl, smb + O_WBL + su);
            mma_f16(Bacc[0], Agh, wbh[0], wbh[1]);
            mma_f16(Bacc[1], Agh, wbh[2], wbh[3]);
            mma_f16(Bacc[0], Agh, wbl[0], wbl[1]);
            mma_f16(Bacc[1], Agh, wbl[2], wbl[3]);
            mma_f16(Bacc[0], Agl, wbh[0], wbh[1]);
            mma_f16(Bacc[1], Agl, wbh[2], wbh[3]);
        }
        if (c < 3) { CP_WAIT0(); __syncthreads(); }
    }

    // ---- cross-warp B reduction (+bb) ----
    __syncthreads();
    {
        float* red = (float*)(sm + O_RED);
        if (h == 1) {
            red[rr * 16 + cb]           = Bacc[0][0];
            red[rr * 16 + cb + 1]       = Bacc[0][1];
            red[rr * 16 + 8 + cb]       = Bacc[1][0];
            red[rr * 16 + 8 + cb + 1]   = Bacc[1][1];
            red[(rr + 8) * 16 + cb]     = Bacc[0][2];
            red[(rr + 8) * 16 + cb + 1] = Bacc[0][3];
            red[(rr + 8) * 16 + 8 + cb]     = Bacc[1][2];
            red[(rr + 8) * 16 + 8 + cb + 1] = Bacc[1][3];
        }
        __syncthreads();
        if (h == 0) {
            float2 bb0 = *(const float2*)(bb + cb);
            float2 bb1 = *(const float2*)(bb + 8 + cb);
            *(float2*)(&g_B[(size_t)(mbase + rr) * 16 + cb]) =
                make_float2(Bacc[0][0] + red[rr * 16 + cb] + bb0.x,
                            Bacc[0][1] + red[rr * 16 + cb + 1] + bb0.y);
            *(float2*)(&g_B[(size_t)(mbase + rr) * 16 + 8 + cb]) =
                make_float2(Bacc[1][0] + red[rr * 16 + 8 + cb] + bb1.x,
                            Bacc[1][1] + red[rr * 16 + 8 + cb + 1] + bb1.y);
            *(float2*)(&g_B[(size_t)(mbase + rr + 8) * 16 + cb]) =
                make_float2(Bacc[0][2] + red[(rr + 8) * 16 + cb] + bb0.x,
                            Bacc[0][3] + red[(rr + 8) * 16 + cb + 1] + bb0.y);
            *(float2*)(&g_B[(size_t)(mbase + rr + 8) * 16 + 8 + cb]) =
                make_float2(Bacc[1][2] + red[(rr + 8) * 16 + 8 + cb] + bb1.x,
                            Bacc[1][3] + red[(rr + 8) * 16 + 8 + cb + 1] + bb1.y);
        }
    }
}

// ---------------------------------------------------------------------------
// MEGA-MID: scan_out [0,2048) + gat1_attn [2048,4096)
// ---------------------------------------------------------------------------
__global__ void mega_mid_kernel(const float* __restrict__ A_log, float* __restrict__ out)
{
    const int blk = blockIdx.x;
    const int tid = threadIdx.x;   // 256
    __shared__ float Bs[L_SEQ * D_STATE];
    __shared__ float Cs[L_SEQ * D_STATE];
    __shared__ unsigned short nbr[MAX_DEG];
    __shared__ float att[HEADS][MAX_DEG];

    if (blk < N_NODES) {
        const int n = blk;
        for (int idx = tid; idx < L_SEQ * D_STATE; idx += 256) {
            Bs[idx] = g_B[(size_t)n * L_SEQ * D_STATE + idx];
            Cs[idx] = g_C[(size_t)n * L_SEQ * D_STATE + idx];
        }
        __syncthreads();
        if (tid < D_STATE) {
            float Av = expf(0.01f * expf(A_log[tid]));
            float h = 0.f;
            for (int t = 0; t < L_SEQ; ++t) {
                h = Av * h + Bs[t * D_STATE + tid];
                Bs[t * D_STATE + tid] = h * Cs[t * D_STATE + tid];
            }
        }
        __syncthreads();
        if (tid < 128) {
            float wc[D_STATE];
            #pragma unroll
            for (int d = 0; d < D_STATE; ++d) wc[d] = g_Wcomb[d * 128 + tid];
            float bj = g_bcomb[tid];
            float* op = out + (size_t)n * L_SEQ * MAMBA_DIM + tid;
            for (int t = 0; t < L_SEQ; ++t) {
                float acc = bj;
                #pragma unroll
                for (int d = 0; d < D_STATE; ++d) acc += Bs[t * D_STATE + d] * wc[d];
                op[(size_t)t * MAMBA_DIM] = acc;
            }
        }
    } else {
        const int i = blk - N_NODES;
        const int m = g_deg[i];
        if (tid < m) nbr[tid] = g_nbr[i * MAX_DEG + tid];
        __syncthreads();

        if (tid < 128) {
            const int h = tid >> 5, lane = tid & 31;
            const float esrc = g_es1[h * N_NODES + i];
            float emax = -1e30f;
            for (int s = lane; s < m; s += 32) {
                float e = esrc + g_ed1[h * N_NODES + (int)nbr[s]];
                e = e > 0.f ? e : 0.2f * e;
                att[h][s] = e;
                emax = fmaxf(emax, e);
            }
            #pragma unroll
            for (int off = 16; off; off >>= 1)
                emax = fmaxf(emax, __shfl_xor_sync(0xffffffffu, emax, off));
            float esum = 0.f;
            for (int s = lane; s < m; s += 32) {
                float v = __expf(att[h][s] - emax);
                att[h][s] = v; esum += v;
            }
            #pragma unroll
            for (int off = 16; off; off >>= 1)
                esum += __shfl_xor_sync(0xffffffffu, esum, off);
            float inv = 1.f / esum;
            for (int s = lane; s < m; s += 32) att[h][s] *= inv;
        }
        __syncthreads();

        const int h = tid >> 6, o = tid & 63;
        float acc = 0.f;
        for (int s = 0; s < m; ++s)
            acc += att[h][s] * g_xt1[((size_t)h * N_NODES + (int)nbr[s]) * 64 + o];
        g_h1[(size_t)i * 256 + h * 64 + o] = fmaxf(acc, 0.f);
    }
}

// ---------------------------------------------------------------------------
// GAT layer 2: transform, 4 nodes/block
// ---------------------------------------------------------------------------
#define GT2_NODES 4
__global__ void gat2_transform_kernel(const float* __restrict__ W2,
                                      const float* __restrict__ a2)
{
    const int n0 = blockIdx.x * GT2_NODES;   // grid 512
    const int tid = threadIdx.x;             // 256
    const int kg = tid >> 6, o = tid & 63;
    __shared__ float hr[GT2_NODES][256];
    __shared__ float part[4][GT2_NODES][64];
    __shared__ float red[2][2][GT2_NODES];

    for (int u = tid; u < GT2_NODES * 256; u += 256)
        hr[u >> 8][u & 255] = g_h1[(size_t)(n0 + (u >> 8)) * 256 + (u & 255)];
    __syncthreads();

    float acc[GT2_NODES];
    #pragma unroll
    for (int r = 0; r < GT2_NODES; ++r) acc[r] = 0.f;
    #pragma unroll 4
    for (int kk = 0; kk < 64; ++kk) {
        int k = kg * 64 + kk;
        float wv = W2[k * 64 + o];
        #pragma unroll
        for (int r = 0; r < GT2_NODES; ++r) acc[r] += hr[r][k] * wv;
    }
    #pragma unroll
    for (int r = 0; r < GT2_NODES; ++r) part[kg][r][o] = acc[r];
    __syncthreads();

    if (kg == 0) {
        const float as = a2[o], ad = a2[64 + o];
        const int wh = o >> 5;
        #pragma unroll
        for (int r = 0; r < GT2_NODES; ++r) {
            float v = part[0][r][o] + part[1][r][o] + part[2][r][o] + part[3][r][o];
            g_xt2[(size_t)(n0 + r) * 64 + o] = v;
            float ps = v * as, pd = v * ad;
            #pragma unroll
            for (int off = 16; off; off >>= 1) {
                ps += __shfl_xor_sync(0xffffffffu, ps, off);
                pd += __shfl_xor_sync(0xffffffffu, pd, off);
            }
            if ((o & 31) == 0) { red[0][wh][r] = ps; red[1][wh][r] = pd; }
        }
    }
    __syncthreads();
    if (tid < GT2_NODES) {
        g_es2[n0 + tid] = red[0][0][tid] + red[0][1][tid];
        g_ed2[n0 + tid] = red[1][0][tid] + red[1][1][tid];
    }
}

// ---------------------------------------------------------------------------
// GAT layer 2: sparse attention + aggregation (split-s: 2 partial sums)
// ---------------------------------------------------------------------------
__global__ void gat2_attn_kernel(float* __restrict__ outg)
{
    const int i = blockIdx.x;
    __shared__ unsigned short nbr[MAX_DEG];
    __shared__ float att[MAX_DEG];
    __shared__ float part[64];
    const int tid = threadIdx.x;   // 128
    const int m = g_deg[i];
    if (tid < m) nbr[tid] = g_nbr[i * MAX_DEG + tid];
    __syncthreads();

    if (tid < 32) {
        const float esrc = g_es2[i];
        float emax = -1e30f;
        for (int s = tid; s < m; s += 32) {
            float e = esrc + g_ed2[(int)nbr[s]];
            e = e > 0.f ? e : 0.2f * e;
            att[s] = e;
            emax = fmaxf(emax, e);
        }
        #pragma unroll
        for (int off = 16; off; off >>= 1)
            emax = fmaxf(emax, __shfl_xor_sync(0xffffffffu, emax, off));
        float esum = 0.f;
        for (int s = tid; s < m; s += 32) {
            float v = __expf(att[s] - emax);
            att[s] = v; esum += v;
        }
        #pragma unroll
        for (int off = 16; off; off >>= 1)
            esum += __shfl_xor_sync(0xffffffffu, esum, off);
        float inv = 1.f / esum;
        for (int s = tid; s < m; s += 32) att[s] *= inv;
    }
    __syncthreads();

    // aggregation: 128 threads, o = tid&63, half = tid>>6 sums s = half, half+2, ...
    {
        const int o = tid & 63, half = tid >> 6;
        float acc = 0.f;
        for (int s = half; s < m; s += 2)
            acc += att[s] * g_xt2[(size_t)((int)nbr[s]) * 64 + o];
        if (half == 1) part[o] = acc;
        __syncthreads();
        if (half == 0)
            outg[(size_t)i * 64 + o] = acc + part[o];
    }
}

// ---------------------------------------------------------------------------
// Launch: 5 kernels
// ---------------------------------------------------------------------------
extern "C" void kernel_launch(void* const* d_in, const int* in_sizes, int n_in,
                              void* d_out, int out_size)
{
    const float* temporal = (const float*)d_in[0];
    const float* graph_x  = (const float*)d_in[1];
    const float* adj      = (const float*)d_in[2];
    const float* pos      = (const float*)d_in[3];
    const float* Wi       = (const float*)d_in[4];
    const float* bi       = (const float*)d_in[5];
    const float* Wg       = (const float*)d_in[6];
    const float* bg       = (const float*)d_in[7];
    const float* A_log    = (const float*)d_in[8];
    const float* Wb       = (const float*)d_in[9];
    const float* bb       = (const float*)d_in[10];
    const float* Wc       = (const float*)d_in[11];
    const float* bc       = (const float*)d_in[12];
    const float* Wo       = (const float*)d_in[13];
    const float* bo       = (const float*)d_in[14];
    const float* Wfc      = (const float*)d_in[15];
    const float* bfc      = (const float*)d_in[16];
    const float* W1       = (const float*)d_in[17];
    const float* a1       = (const float*)d_in[18];
    const float* W2       = (const float*)d_in[19];
    const float* a2       = (const float*)d_in[20];

    float* out_mamba = (float*)d_out;
    float* out_gat   = out_mamba + (size_t)N_NODES * L_SEQ * MAMBA_DIM;

    cudaFuncSetAttribute(mamba_mma_kernel,
                         cudaFuncAttributeMaxDynamicSharedMemorySize, SMEM_MAMBA);

    mega_prep_kernel<<<GRID_PREP, 256>>>(
        temporal, pos, Wi, Wg, Wb, Wc, Wo, bo, Wfc, bfc);           // idx 0
    mamba_mma_kernel<<<GRID_MAMBA, 512, SMEM_MAMBA>>>(
        bi, bg, bb, bc, adj, graph_x, W1, a1);                      // idx 1
    mega_mid_kernel<<<2 * N_NODES, 256>>>(A_log, out_mamba);        // idx 2
    gat2_transform_kernel<<<N_NODES / GT2_NODES, 256>>>(W2, a2);    // idx 3
    gat2_attn_kernel<<<N_NODES, 128>>>(out_gat);                    // idx 4
}